// round 1
// baseline (speedup 1.0000x reference)
#include <cuda_runtime.h>

#define NSEG 16384
#define DFEAT 128
#define EPSV 1e-10f
#define ROWS_PER_WARP 64

// Scratch (allocation-free requirement -> __device__ globals)
__device__ float g_pooled[NSEG * DFEAT];   // 8 MB
__device__ float g_denom[NSEG];

// ---------------------------------------------------------------------------
// Kernel 0: zero the scratch accumulators
// ---------------------------------------------------------------------------
__global__ void zero_scratch_kernel() {
    int i = blockIdx.x * blockDim.x + threadIdx.x;
    if (i < NSEG * DFEAT) g_pooled[i] = 0.0f;
    if (i < NSEG)         g_denom[i]  = 0.0f;
}

// ---------------------------------------------------------------------------
// Kernel 1: fused gate + weighted segment pooling.
// One warp handles ROWS_PER_WARP consecutive rows. Since `index` is sorted,
// segment changes are rare (~once per 61 rows): accumulate in registers and
// flush via atomics only at boundaries.
// Per row: g = x_row . gate_w + gate_b (warp butterfly reduce),
//          e = weights^pow_p * exp(g),
//          acc += e * x_row (float4 per lane), dsum += e.
// No per-segment max subtraction: g ~ N(0,1), exp is safe, and the eps-term
// perturbation is O(1e-11) relative — far below the 1e-3 tolerance.
// ---------------------------------------------------------------------------
__global__ void __launch_bounds__(256) gate_pool_kernel(
    const float4* __restrict__ x4,        // [N, 32] float4 view of [N,128]
    const int*    __restrict__ index,     // [N] sorted
    const float*  __restrict__ weights,   // [N]
    const float*  __restrict__ gate_w,    // [128]
    const float*  __restrict__ gate_b,    // [1]
    const float*  __restrict__ pow_p,     // [1]
    int n_rows)
{
    const int lane = threadIdx.x & 31;
    const int warp_global = (blockIdx.x * blockDim.x + threadIdx.x) >> 5;
    const int row0 = warp_global * ROWS_PER_WARP;
    if (row0 >= n_rows) return;
    const int row_end = min(n_rows, row0 + ROWS_PER_WARP);

    const float4 gw = reinterpret_cast<const float4*>(gate_w)[lane];
    const float gb = __ldg(gate_b);
    const float p  = __ldg(pow_p);

    float4 acc = make_float4(0.f, 0.f, 0.f, 0.f);
    float dsum = 0.f;
    int cur = __ldg(&index[row0]);

    for (int r = row0; r < row_end; ++r) {
        const int seg = __ldg(&index[r]);           // uniform across warp
        const float4 xv = x4[(size_t)r * 32 + lane];
        const float w = __ldg(&weights[r]);

        float part = xv.x * gw.x + xv.y * gw.y + xv.z * gw.z + xv.w * gw.w;
        #pragma unroll
        for (int off = 16; off; off >>= 1)
            part += __shfl_xor_sync(0xffffffffu, part, off);
        // part is the full dot product on every lane (butterfly)
        const float e = __powf(w, p) * __expf(part + gb);

        if (seg != cur) {
            float* dst = &g_pooled[cur * DFEAT + lane * 4];
            atomicAdd(dst + 0, acc.x);
            atomicAdd(dst + 1, acc.y);
            atomicAdd(dst + 2, acc.z);
            atomicAdd(dst + 3, acc.w);
            if (lane == 0) atomicAdd(&g_denom[cur], dsum);
            acc = make_float4(0.f, 0.f, 0.f, 0.f);
            dsum = 0.f;
            cur = seg;
        }
        acc.x += e * xv.x;
        acc.y += e * xv.y;
        acc.z += e * xv.z;
        acc.w += e * xv.w;
        dsum += e;
    }
    // final flush
    {
        float* dst = &g_pooled[cur * DFEAT + lane * 4];
        atomicAdd(dst + 0, acc.x);
        atomicAdd(dst + 1, acc.y);
        atomicAdd(dst + 2, acc.z);
        atomicAdd(dst + 3, acc.w);
        if (lane == 0) atomicAdd(&g_denom[cur], dsum);
    }
}

// ---------------------------------------------------------------------------
// Kernel 2: out[s] = (pooled[s]/(denom[s]+eps)) @ msg_w
//                    + (denom[s]/(denom[s]+eps)) * msg_b
// 16 segments per block, 256 threads.
// Thread layout: c = tid&31 -> 4 output cols (float4), rg = tid>>5 -> 2 rows.
// msg_w is 64 KB and reused by every block -> L1/L2 resident.
// ---------------------------------------------------------------------------
__global__ void __launch_bounds__(256) out_gemm_kernel(
    const float* __restrict__ msg_w,      // [128,128] row-major (k, n)
    const float* __restrict__ msg_b,      // [128]
    float*       __restrict__ out)        // [NSEG,128]
{
    __shared__ float pr[16][DFEAT];       // normalized pooled rows
    __shared__ float gsh[16];             // sum of gate per segment

    const int s0 = blockIdx.x * 16;
    const int tid = threadIdx.x;

    #pragma unroll
    for (int i = tid; i < 16 * DFEAT; i += 256) {
        const int rr = i >> 7;
        const float den = g_denom[s0 + rr];
        pr[rr][i & 127] = g_pooled[(s0 + rr) * DFEAT + (i & 127)] / (den + EPSV);
    }
    if (tid < 16) {
        const float den = g_denom[s0 + tid];
        gsh[tid] = den / (den + EPSV);
    }
    __syncthreads();

    const int c  = tid & 31;              // column group (4 cols)
    const int rg = tid >> 5;              // row group (2 rows)
    const int r0 = rg * 2;
    const int r1 = rg * 2 + 1;

    const float4* mw4 = reinterpret_cast<const float4*>(msg_w);
    const float4  mb  = reinterpret_cast<const float4*>(msg_b)[c];

    float4 a0 = make_float4(0.f, 0.f, 0.f, 0.f);
    float4 a1 = make_float4(0.f, 0.f, 0.f, 0.f);

    #pragma unroll 4
    for (int k = 0; k < DFEAT; ++k) {
        const float4 m = mw4[k * 32 + c];
        const float p0 = pr[r0][k];
        const float p1 = pr[r1][k];
        a0.x += p0 * m.x; a0.y += p0 * m.y; a0.z += p0 * m.z; a0.w += p0 * m.w;
        a1.x += p1 * m.x; a1.y += p1 * m.y; a1.z += p1 * m.z; a1.w += p1 * m.w;
    }

    const float g0 = gsh[r0];
    const float g1 = gsh[r1];
    float4 o0 = make_float4(a0.x + g0 * mb.x, a0.y + g0 * mb.y,
                            a0.z + g0 * mb.z, a0.w + g0 * mb.w);
    float4 o1 = make_float4(a1.x + g1 * mb.x, a1.y + g1 * mb.y,
                            a1.z + g1 * mb.z, a1.w + g1 * mb.w);

    reinterpret_cast<float4*>(out)[(size_t)(s0 + r0) * 32 + c] = o0;
    reinterpret_cast<float4*>(out)[(size_t)(s0 + r1) * 32 + c] = o1;
}

// ---------------------------------------------------------------------------
// Launch. Input order (metadata): x, index, weights, gate_w, gate_b,
//                                 msg_w, msg_b, pow_p. Output: [16384,128] f32.
// ---------------------------------------------------------------------------
extern "C" void kernel_launch(void* const* d_in, const int* in_sizes, int n_in,
                              void* d_out, int out_size)
{
    const float* x       = (const float*)d_in[0];
    const int*   index   = (const int*)  d_in[1];
    const float* weights = (const float*)d_in[2];
    const float* gate_w  = (const float*)d_in[3];
    const float* gate_b  = (const float*)d_in[4];
    const float* msg_w   = (const float*)d_in[5];
    const float* msg_b   = (const float*)d_in[6];
    const float* pow_p   = (const float*)d_in[7];
    float* out = (float*)d_out;

    const int n_rows = in_sizes[1];

    // 0) zero scratch
    {
        const int total = NSEG * DFEAT;
        zero_scratch_kernel<<<(total + 255) / 256, 256>>>();
    }

    // 1) fused gate + pooling
    {
        const int n_warps  = (n_rows + ROWS_PER_WARP - 1) / ROWS_PER_WARP;
        const int n_blocks = (n_warps + 7) / 8;             // 8 warps / block
        gate_pool_kernel<<<n_blocks, 256>>>(
            (const float4*)x, index, weights, gate_w, gate_b, pow_p, n_rows);
    }

    // 2) small GEMM epilogue
    {
        out_gemm_kernel<<<NSEG / 16, 256>>>(msg_w, msg_b, out);
    }
}

// round 2
// speedup vs baseline: 1.4150x; 1.4150x over previous
#include <cuda_runtime.h>

#define NSEG 16384
#define DFEAT 128
#define EPSV 1e-10f
#define ROWS_PER_WARP 64
#define RB 8                    // row batch (ILP depth)

// Scratch (allocation-free requirement -> __device__ globals)
__device__ float g_pooled[NSEG * DFEAT];   // 8 MB
__device__ float g_denom[NSEG];

// ---------------------------------------------------------------------------
// Kernel 0: zero the scratch accumulators (float4, 4 elems/thread)
// ---------------------------------------------------------------------------
__global__ void zero_scratch_kernel() {
    const int i = blockIdx.x * blockDim.x + threadIdx.x;
    float4* p4 = reinterpret_cast<float4*>(g_pooled);
    if (i < NSEG * DFEAT / 4) p4[i] = make_float4(0.f, 0.f, 0.f, 0.f);
    if (i < NSEG / 4) reinterpret_cast<float4*>(g_denom)[i] = make_float4(0.f, 0.f, 0.f, 0.f);
}

// ---------------------------------------------------------------------------
// Kernel 1: fused gate + weighted segment pooling, 8-row ILP batches.
// One warp handles ROWS_PER_WARP consecutive rows in batches of RB=8:
//   - 8 float4 loads issued back-to-back (MLP=8 per warp)
//   - 8 independent butterfly-reduce chains (latency overlapped)
//   - since index is sorted, batch is boundary-free iff seg[RB-1]==cur
// Flush via atomicAdd only at segment boundaries (~1 per 61 rows).
// No per-segment max subtraction: g ~ N(0,1), exp safe; eps-term error ~1e-11.
// ---------------------------------------------------------------------------
__global__ void __launch_bounds__(256) gate_pool_kernel(
    const float4* __restrict__ x4,        // [N, 32] float4 view of [N,128]
    const int*    __restrict__ index,     // [N] sorted
    const float*  __restrict__ weights,   // [N]
    const float*  __restrict__ gate_w,    // [128]
    const float*  __restrict__ gate_b,    // [1]
    const float*  __restrict__ pow_p,     // [1]
    int n_rows)
{
    const int lane = threadIdx.x & 31;
    const int warp_global = (blockIdx.x * blockDim.x + threadIdx.x) >> 5;
    const int row0 = warp_global * ROWS_PER_WARP;
    if (row0 >= n_rows) return;
    const int row_end = min(n_rows, row0 + ROWS_PER_WARP);

    const float4 gw = reinterpret_cast<const float4*>(gate_w)[lane];
    const float gb = __ldg(gate_b);
    const float p  = __ldg(pow_p);

    float4 acc = make_float4(0.f, 0.f, 0.f, 0.f);
    float dsum = 0.f;
    int cur = __ldg(&index[row0]);

    int r = row0;
    // ---- full 8-row batches ----
    for (; r + RB <= row_end; r += RB) {
        float4 xv[RB];
        float  part[RB];
        float  w[RB];
        int    seg[RB];
        #pragma unroll
        for (int j = 0; j < RB; ++j) {
            xv[j]  = x4[(size_t)(r + j) * 32 + lane];
            seg[j] = __ldg(&index[r + j]);
            w[j]   = __ldg(&weights[r + j]);
        }
        #pragma unroll
        for (int j = 0; j < RB; ++j)
            part[j] = xv[j].x * gw.x + xv[j].y * gw.y + xv[j].z * gw.z + xv[j].w * gw.w;
        #pragma unroll
        for (int off = 16; off; off >>= 1) {
            #pragma unroll
            for (int j = 0; j < RB; ++j)
                part[j] += __shfl_xor_sync(0xffffffffu, part[j], off);
        }
        float e[RB];
        #pragma unroll
        for (int j = 0; j < RB; ++j)
            e[j] = __powf(w[j], p) * __expf(part[j] + gb);

        if (seg[RB - 1] == cur) {
            // sorted + last == cur  =>  all == cur  (fast path)
            #pragma unroll
            for (int j = 0; j < RB; ++j) {
                acc.x += e[j] * xv[j].x;
                acc.y += e[j] * xv[j].y;
                acc.z += e[j] * xv[j].z;
                acc.w += e[j] * xv[j].w;
                dsum  += e[j];
            }
        } else {
            #pragma unroll
            for (int j = 0; j < RB; ++j) {
                if (seg[j] != cur) {
                    float* dst = &g_pooled[cur * DFEAT + lane * 4];
                    atomicAdd(dst + 0, acc.x);
                    atomicAdd(dst + 1, acc.y);
                    atomicAdd(dst + 2, acc.z);
                    atomicAdd(dst + 3, acc.w);
                    if (lane == 0) atomicAdd(&g_denom[cur], dsum);
                    acc = make_float4(0.f, 0.f, 0.f, 0.f);
                    dsum = 0.f;
                    cur = seg[j];
                }
                acc.x += e[j] * xv[j].x;
                acc.y += e[j] * xv[j].y;
                acc.z += e[j] * xv[j].z;
                acc.w += e[j] * xv[j].w;
                dsum  += e[j];
            }
        }
    }
    // ---- tail rows (n_rows not multiple of RB) ----
    for (; r < row_end; ++r) {
        const int seg = __ldg(&index[r]);
        const float4 xv = x4[(size_t)r * 32 + lane];
        const float w = __ldg(&weights[r]);
        float part = xv.x * gw.x + xv.y * gw.y + xv.z * gw.z + xv.w * gw.w;
        #pragma unroll
        for (int off = 16; off; off >>= 1)
            part += __shfl_xor_sync(0xffffffffu, part, off);
        const float e = __powf(w, p) * __expf(part + gb);
        if (seg != cur) {
            float* dst = &g_pooled[cur * DFEAT + lane * 4];
            atomicAdd(dst + 0, acc.x);
            atomicAdd(dst + 1, acc.y);
            atomicAdd(dst + 2, acc.z);
            atomicAdd(dst + 3, acc.w);
            if (lane == 0) atomicAdd(&g_denom[cur], dsum);
            acc = make_float4(0.f, 0.f, 0.f, 0.f);
            dsum = 0.f;
            cur = seg;
        }
        acc.x += e * xv.x;
        acc.y += e * xv.y;
        acc.z += e * xv.z;
        acc.w += e * xv.w;
        dsum += e;
    }
    // final flush
    {
        float* dst = &g_pooled[cur * DFEAT + lane * 4];
        atomicAdd(dst + 0, acc.x);
        atomicAdd(dst + 1, acc.y);
        atomicAdd(dst + 2, acc.z);
        atomicAdd(dst + 3, acc.w);
        if (lane == 0) atomicAdd(&g_denom[cur], dsum);
    }
}

// ---------------------------------------------------------------------------
// Kernel 2: out[s] = (pooled[s]/(denom[s]+eps)) @ msg_w
//                    + (denom[s]/(denom[s]+eps)) * msg_b
// 16 segments per block, 256 threads; msg_w (64 KB) L1/L2 resident.
// ---------------------------------------------------------------------------
__global__ void __launch_bounds__(256) out_gemm_kernel(
    const float* __restrict__ msg_w,      // [128,128] row-major (k, n)
    const float* __restrict__ msg_b,      // [128]
    float*       __restrict__ out)        // [NSEG,128]
{
    __shared__ float pr[16][DFEAT];       // normalized pooled rows
    __shared__ float gsh[16];             // denom/(denom+eps) per segment

    const int s0 = blockIdx.x * 16;
    const int tid = threadIdx.x;

    #pragma unroll
    for (int i = tid; i < 16 * DFEAT; i += 256) {
        const int rr = i >> 7;
        const float den = g_denom[s0 + rr];
        pr[rr][i & 127] = g_pooled[(s0 + rr) * DFEAT + (i & 127)] / (den + EPSV);
    }
    if (tid < 16) {
        const float den = g_denom[s0 + tid];
        gsh[tid] = den / (den + EPSV);
    }
    __syncthreads();

    const int c  = tid & 31;              // column group (4 cols)
    const int rg = tid >> 5;              // row group (2 rows)
    const int r0 = rg * 2;
    const int r1 = rg * 2 + 1;

    const float4* mw4 = reinterpret_cast<const float4*>(msg_w);
    const float4  mb  = reinterpret_cast<const float4*>(msg_b)[c];

    float4 a0 = make_float4(0.f, 0.f, 0.f, 0.f);
    float4 a1 = make_float4(0.f, 0.f, 0.f, 0.f);

    #pragma unroll 4
    for (int k = 0; k < DFEAT; ++k) {
        const float4 m = mw4[k * 32 + c];
        const float p0 = pr[r0][k];
        const float p1 = pr[r1][k];
        a0.x += p0 * m.x; a0.y += p0 * m.y; a0.z += p0 * m.z; a0.w += p0 * m.w;
        a1.x += p1 * m.x; a1.y += p1 * m.y; a1.z += p1 * m.z; a1.w += p1 * m.w;
    }

    const float g0 = gsh[r0];
    const float g1 = gsh[r1];
    float4 o0 = make_float4(a0.x + g0 * mb.x, a0.y + g0 * mb.y,
                            a0.z + g0 * mb.z, a0.w + g0 * mb.w);
    float4 o1 = make_float4(a1.x + g1 * mb.x, a1.y + g1 * mb.y,
                            a1.z + g1 * mb.z, a1.w + g1 * mb.w);

    reinterpret_cast<float4*>(out)[(size_t)(s0 + r0) * 32 + c] = o0;
    reinterpret_cast<float4*>(out)[(size_t)(s0 + r1) * 32 + c] = o1;
}

// ---------------------------------------------------------------------------
// Launch. Inputs: x, index, weights, gate_w, gate_b, msg_w, msg_b, pow_p.
// Output: [16384,128] f32.
// ---------------------------------------------------------------------------
extern "C" void kernel_launch(void* const* d_in, const int* in_sizes, int n_in,
                              void* d_out, int out_size)
{
    const float* x       = (const float*)d_in[0];
    const int*   index   = (const int*)  d_in[1];
    const float* weights = (const float*)d_in[2];
    const float* gate_w  = (const float*)d_in[3];
    const float* gate_b  = (const float*)d_in[4];
    const float* msg_w   = (const float*)d_in[5];
    const float* msg_b   = (const float*)d_in[6];
    const float* pow_p   = (const float*)d_in[7];
    float* out = (float*)d_out;

    const int n_rows = in_sizes[1];

    // 0) zero scratch (float4 stores)
    {
        const int total4 = NSEG * DFEAT / 4;   // 524288
        zero_scratch_kernel<<<(total4 + 255) / 256, 256>>>();
    }

    // 1) fused gate + pooling
    {
        const int n_warps  = (n_rows + ROWS_PER_WARP - 1) / ROWS_PER_WARP;
        const int n_blocks = (n_warps + 7) / 8;             // 8 warps / block
        gate_pool_kernel<<<n_blocks, 256>>>(
            (const float4*)x, index, weights, gate_w, gate_b, pow_p, n_rows);
    }

    // 2) small GEMM epilogue
    {
        out_gemm_kernel<<<NSEG / 16, 256>>>(msg_w, msg_b, out);
    }
}

// round 4
// speedup vs baseline: 1.4398x; 1.0176x over previous
#include <cuda_runtime.h>

#define NSEG 16384
#define DFEAT 128
#define EPSV 1e-10f
#define RPW 64                  // rows per warp
#define RB 8                    // row batch (ILP depth)

// Scratch (allocation-free requirement -> __device__ globals)
__device__ float g_pooled[NSEG * DFEAT];   // 8 MB
__device__ float g_denom[NSEG];

// ---------------------------------------------------------------------------
// Kernel 0: zero the scratch accumulators (grid-stride float4)
// ---------------------------------------------------------------------------
__global__ void zero_scratch_kernel() {
    const int stride = gridDim.x * blockDim.x;
    const float4 z = make_float4(0.f, 0.f, 0.f, 0.f);
    float4* p4 = reinterpret_cast<float4*>(g_pooled);
    for (int i = blockIdx.x * blockDim.x + threadIdx.x;
         i < NSEG * DFEAT / 4; i += stride)
        p4[i] = z;
    float4* d4 = reinterpret_cast<float4*>(g_denom);
    for (int i = blockIdx.x * blockDim.x + threadIdx.x;
         i < NSEG / 4; i += stride)
        d4[i] = z;
}

// ---------------------------------------------------------------------------
// Kernel 1: fused gate + weighted segment pooling.
// Software-pipelined 8-row batches: loads for batch i+1 are issued before
// the compute of batch i, so each warp keeps ~8 512B loads in flight
// continuously instead of stalling memory-silent through the shfl/MUFU chain.
// Fast path uses only index[r+RB-1] (sorted => uniform batch test); the rare
// boundary path re-reads index from L1.
// pow+exp fused: w^p * e^g = e^(p*ln(w) + g)  (LG2 + EX2, 2 MUFU).
// ---------------------------------------------------------------------------
__global__ void __launch_bounds__(128, 4) gate_pool_kernel(
    const float4* __restrict__ x4,        // [N, 32] float4 view of [N,128]
    const int*    __restrict__ index,     // [N] sorted
    const float*  __restrict__ weights,   // [N]
    const float*  __restrict__ gate_w,    // [128]
    const float*  __restrict__ gate_b,    // [1]
    const float*  __restrict__ pow_p,     // [1]
    int n_rows)
{
    const int lane = threadIdx.x & 31;
    const int warp_global = (blockIdx.x * blockDim.x + threadIdx.x) >> 5;
    const int row0 = warp_global * RPW;
    if (row0 >= n_rows) return;

    const float4 gw = reinterpret_cast<const float4*>(gate_w)[lane];
    const float gb = __ldg(gate_b);
    const float p  = __ldg(pow_p);

    float4 acc = make_float4(0.f, 0.f, 0.f, 0.f);
    float dsum = 0.f;
    int cur = __ldg(&index[row0]);

    auto flush = [&]() {
        float* dst = &g_pooled[cur * DFEAT + lane * 4];
        atomicAdd(dst + 0, acc.x);
        atomicAdd(dst + 1, acc.y);
        atomicAdd(dst + 2, acc.z);
        atomicAdd(dst + 3, acc.w);
        if (lane == 0) atomicAdd(&g_denom[cur], dsum);
        acc = make_float4(0.f, 0.f, 0.f, 0.f);
        dsum = 0.f;
    };

    if (row0 + RPW <= n_rows) {
        // ---------------- full-warp pipelined path ----------------
        float4 xvA[RB], xvB[RB];
        float  wA[RB],  wB[RB];
        int    segLastA, segLastB;

        auto load = [&](float4* xv, float* w, int& segLast, int r) {
            #pragma unroll
            for (int j = 0; j < RB; ++j)
                xv[j] = x4[(size_t)(r + j) * 32 + lane];
            #pragma unroll
            for (int j = 0; j < RB; ++j)
                w[j] = __ldg(&weights[r + j]);
            segLast = __ldg(&index[r + RB - 1]);
        };

        auto compute = [&](const float4* xv, const float* w, int segLast, int r) {
            float part[RB];
            #pragma unroll
            for (int j = 0; j < RB; ++j)
                part[j] = xv[j].x * gw.x + xv[j].y * gw.y
                        + xv[j].z * gw.z + xv[j].w * gw.w;
            #pragma unroll
            for (int off = 16; off; off >>= 1) {
                #pragma unroll
                for (int j = 0; j < RB; ++j)
                    part[j] += __shfl_xor_sync(0xffffffffu, part[j], off);
            }
            float e[RB];
            #pragma unroll
            for (int j = 0; j < RB; ++j)
                e[j] = __expf(__fmaf_rn(p, __logf(w[j]), part[j] + gb));
            if (segLast == cur) {
                // sorted + last == cur  =>  whole batch == cur
                #pragma unroll
                for (int j = 0; j < RB; ++j) {
                    acc.x += e[j] * xv[j].x;
                    acc.y += e[j] * xv[j].y;
                    acc.z += e[j] * xv[j].z;
                    acc.w += e[j] * xv[j].w;
                    dsum  += e[j];
                }
            } else {
                #pragma unroll
                for (int j = 0; j < RB; ++j) {
                    const int seg = __ldg(&index[r + j]);   // L1-hot
                    if (seg != cur) { flush(); cur = seg; }
                    acc.x += e[j] * xv[j].x;
                    acc.y += e[j] * xv[j].y;
                    acc.z += e[j] * xv[j].z;
                    acc.w += e[j] * xv[j].w;
                    dsum  += e[j];
                }
            }
        };

        load(xvA, wA, segLastA, row0);
        #pragma unroll
        for (int b = 0; b < RPW / (2 * RB); ++b) {
            const int rA = row0 + (2 * b) * RB;
            const int rB = row0 + (2 * b + 1) * RB;
            load(xvB, wB, segLastB, rB);
            compute(xvA, wA, segLastA, rA);
            if (2 * b + 2 < RPW / RB)
                load(xvA, wA, segLastA, row0 + (2 * b + 2) * RB);
            compute(xvB, wB, segLastB, rB);
        }
    } else {
        // ---------------- ragged tail path ----------------
        const int row_end = min(n_rows, row0 + RPW);
        for (int r = row0; r < row_end; ++r) {
            const int seg = __ldg(&index[r]);
            const float4 xv = x4[(size_t)r * 32 + lane];
            const float w = __ldg(&weights[r]);
            float part = xv.x * gw.x + xv.y * gw.y + xv.z * gw.z + xv.w * gw.w;
            #pragma unroll
            for (int off = 16; off; off >>= 1)
                part += __shfl_xor_sync(0xffffffffu, part, off);
            const float e = __expf(__fmaf_rn(p, __logf(w), part + gb));
            if (seg != cur) { flush(); cur = seg; }
            acc.x += e * xv.x;
            acc.y += e * xv.y;
            acc.z += e * xv.z;
            acc.w += e * xv.w;
            dsum += e;
        }
    }
    flush();
}

// ---------------------------------------------------------------------------
// Kernel 2: out[s] = (pooled[s]/(denom[s]+eps)) @ msg_w
//                    + (denom[s]/(denom[s]+eps)) * msg_b
// 16 segments per block, 256 threads; msg_w (64 KB) L1/L2 resident.
// ---------------------------------------------------------------------------
__global__ void __launch_bounds__(256) out_gemm_kernel(
    const float* __restrict__ msg_w,      // [128,128] row-major (k, n)
    const float* __restrict__ msg_b,      // [128]
    float*       __restrict__ out)        // [NSEG,128]
{
    __shared__ float pr[16][DFEAT];       // normalized pooled rows
    __shared__ float gsh[16];             // denom/(denom+eps) per segment

    const int s0 = blockIdx.x * 16;
    const int tid = threadIdx.x;

    #pragma unroll
    for (int i = tid; i < 16 * DFEAT; i += 256) {
        const int rr = i >> 7;
        const float den = g_denom[s0 + rr];
        pr[rr][i & 127] = g_pooled[(s0 + rr) * DFEAT + (i & 127)] / (den + EPSV);
    }
    if (tid < 16) {
        const float den = g_denom[s0 + tid];
        gsh[tid] = den / (den + EPSV);
    }
    __syncthreads();

    const int c  = tid & 31;              // column group (4 cols)
    const int rg = tid >> 5;              // row group (2 rows)
    const int r0 = rg * 2;
    const int r1 = rg * 2 + 1;

    const float4* mw4 = reinterpret_cast<const float4*>(msg_w);
    const float4  mb  = reinterpret_cast<const float4*>(msg_b)[c];

    float4 a0 = make_float4(0.f, 0.f, 0.f, 0.f);
    float4 a1 = make_float4(0.f, 0.f, 0.f, 0.f);

    #pragma unroll 4
    for (int k = 0; k < DFEAT; ++k) {
        const float4 m = mw4[k * 32 + c];
        const float p0 = pr[r0][k];
        const float p1 = pr[r1][k];
        a0.x += p0 * m.x; a0.y += p0 * m.y; a0.z += p0 * m.z; a0.w += p0 * m.w;
        a1.x += p1 * m.x; a1.y += p1 * m.y; a1.z += p1 * m.z; a1.w += p1 * m.w;
    }

    const float g0 = gsh[r0];
    const float g1 = gsh[r1];
    float4 o0 = make_float4(a0.x + g0 * mb.x, a0.y + g0 * mb.y,
                            a0.z + g0 * mb.z, a0.w + g0 * mb.w);
    float4 o1 = make_float4(a1.x + g1 * mb.x, a1.y + g1 * mb.y,
                            a1.z + g1 * mb.z, a1.w + g1 * mb.w);

    reinterpret_cast<float4*>(out)[(size_t)(s0 + r0) * 32 + c] = o0;
    reinterpret_cast<float4*>(out)[(size_t)(s0 + r1) * 32 + c] = o1;
}

// ---------------------------------------------------------------------------
// Launch. Inputs: x, index, weights, gate_w, gate_b, msg_w, msg_b, pow_p.
// Output: [16384,128] f32.
// ---------------------------------------------------------------------------
extern "C" void kernel_launch(void* const* d_in, const int* in_sizes, int n_in,
                              void* d_out, int out_size)
{
    const float* x       = (const float*)d_in[0];
    const int*   index   = (const int*)  d_in[1];
    const float* weights = (const float*)d_in[2];
    const float* gate_w  = (const float*)d_in[3];
    const float* gate_b  = (const float*)d_in[4];
    const float* msg_w   = (const float*)d_in[5];
    const float* msg_b   = (const float*)d_in[6];
    const float* pow_p   = (const float*)d_in[7];
    float* out = (float*)d_out;

    const int n_rows = in_sizes[1];

    // 0) zero scratch
    zero_scratch_kernel<<<256, 256>>>();

    // 1) fused gate + pooling (pipelined)
    {
        const int n_warps  = (n_rows + RPW - 1) / RPW;
        const int n_blocks = (n_warps + 3) / 4;             // 4 warps / block
        gate_pool_kernel<<<n_blocks, 128>>>(
            (const float4*)x, index, weights, gate_w, gate_b, pow_p, n_rows);
    }

    // 2) small GEMM epilogue
    out_gemm_kernel<<<NSEG / 16, 256>>>(msg_w, msg_b, out);
}